// round 17
// baseline (speedup 1.0000x reference)
#include <cuda_runtime.h>
#include <cuda_bf16.h>
#include <cuda_fp16.h>
#include <math.h>
#include <stdint.h>

#define Bn 1024
#define In 512
#define Hn 2048
#define On 512
#define En 8
#define EBO (En * Bn * On)

// ---------------- scratch (device globals; zero-init, 16B aligned; ~96MB proven budget) ----------------
__device__ __align__(16) int   g_counts[En];
__device__ __align__(16) int   g_tok[En * Bn];
__device__ __align__(16) int   g_pos[Bn * 2];
__device__ __align__(16) float g_wk[Bn * 2];
__device__ __align__(16) __half g_hf16[En * Bn * Hn];        // 32 MB (fp16 hidden)
__device__ __align__(16) float g_yall[4 * EBO];              // 64 MB (4 K-quarters)

// ---------------- mma / ldmatrix / cp.async helpers ----------------
__device__ __forceinline__ void mma_f16(float* c, const uint32_t* a, const uint32_t* b) {
    asm volatile(
        "mma.sync.aligned.m16n8k16.row.col.f32.f16.f16.f32 "
        "{%0,%1,%2,%3}, {%4,%5,%6,%7}, {%8,%9}, {%0,%1,%2,%3};"
        : "+f"(c[0]), "+f"(c[1]), "+f"(c[2]), "+f"(c[3])
        : "r"(a[0]), "r"(a[1]), "r"(a[2]), "r"(a[3]), "r"(b[0]), "r"(b[1]));
}
__device__ __forceinline__ void ldsm_x4(uint32_t& r0, uint32_t& r1, uint32_t& r2, uint32_t& r3,
                                        uint32_t addr) {
    asm volatile("ldmatrix.sync.aligned.m8n8.x4.shared.b16 {%0,%1,%2,%3}, [%4];"
        : "=r"(r0), "=r"(r1), "=r"(r2), "=r"(r3) : "r"(addr));
}
#define CP16(dst, src) asm volatile("cp.async.cg.shared.global [%0], [%1], 16;" :: "r"(dst), "l"(src))
#define CPCOMMIT()     asm volatile("cp.async.commit_group;" ::: "memory")
#define CPWAIT1()      asm volatile("cp.async.wait_group 1;" ::: "memory")
#define CPWAIT0()      asm volatile("cp.async.wait_group 0;" ::: "memory")

__device__ __forceinline__ uint32_t pack2h(float a, float b) {
    __half2 v = __floats2half2_rn(a, b);
    return *reinterpret_cast<uint32_t*>(&v);
}

// ---------------- pad-free swizzled smem planes (proven R9-R16) ----------------
// plane: rows x 32 k fp16 = 64 B/row = 4 chunks of 16 B. phys(r,c) = r*64 + ((c ^ ((r>>1)&3))*16)
#define SWZ_R(r) (((r) >> 1) & 3)

#define PLANE_A1 8192                     // gemm1 A: 128 rows fp16
#define PLANE_B1 4096                     // gemm1 B: 64 rows
#define BUF1_B   (PLANE_A1 + PLANE_B1)    // 12288
#define GSMEM1   (2 * BUF1_B)             // 24576 double buffer

#define PLANE_A2 4096                     // gemm2 A: 64 rows fp16
#define PLANE_B2 8192                     // gemm2 B: 128 rows fp16
#define BUF2_B   (PLANE_A2 + PLANE_B2)    // 12288
#define GSMEM2   (3 * BUF2_B)             // 36864 triple buffer

// ---------------- kernel 0: zero counters ----------------
__global__ void zero_counts_kernel() {
    if (threadIdx.x < En) g_counts[threadIdx.x] = 0;
}

// ---------------- kernel 1: gating (proven) ----------------
__global__ void gate_kernel(const float* __restrict__ x,
                            const float* __restrict__ Wg,
                            const float* __restrict__ bg) {
    int warp = threadIdx.x >> 5, lane = threadIdx.x & 31;
    int b = blockIdx.x * 8 + warp;
    const float* xr = x + (size_t)b * In;

    float acc[En];
#pragma unroll
    for (int e = 0; e < En; e++) acc[e] = 0.f;
    for (int i = lane; i < In; i += 32) {
        float xv = xr[i];
        const float4* w4 = reinterpret_cast<const float4*>(Wg + (size_t)i * En);
        float4 w0 = w4[0], w1 = w4[1];
        acc[0] += xv * w0.x; acc[1] += xv * w0.y;
        acc[2] += xv * w0.z; acc[3] += xv * w0.w;
        acc[4] += xv * w1.x; acc[5] += xv * w1.y;
        acc[6] += xv * w1.z; acc[7] += xv * w1.w;
    }
#pragma unroll
    for (int e = 0; e < En; e++) {
#pragma unroll
        for (int off = 16; off; off >>= 1)
            acc[e] += __shfl_xor_sync(0xffffffffu, acc[e], off);
    }
    if (lane == 0) {
        float lg[En]; float m = -1e30f;
#pragma unroll
        for (int e = 0; e < En; e++) { lg[e] = acc[e] + bg[e]; m = fmaxf(m, lg[e]); }
        float p[En]; float s = 0.f;
#pragma unroll
        for (int e = 0; e < En; e++) { p[e] = expf(lg[e] - m); s += p[e]; }
#pragma unroll
        for (int e = 0; e < En; e++) p[e] /= s;
        int i0 = 0;
#pragma unroll
        for (int e = 1; e < En; e++) if (p[e] > p[i0]) i0 = e;
        int i1 = (i0 == 0) ? 1 : 0;
#pragma unroll
        for (int e = 0; e < En; e++) if (e != i0 && p[e] > p[i1]) i1 = e;
        float sum2 = p[i0] + p[i1];
        float w0 = p[i0] / sum2, w1 = p[i1] / sum2;
        int s0 = atomicAdd(&g_counts[i0], 1);
        g_tok[i0 * Bn + s0] = b;
        g_pos[b * 2 + 0] = i0 * Bn + s0;
        g_wk[b * 2 + 0] = w0;
        int s1 = atomicAdd(&g_counts[i1], 1);
        g_tok[i1 * Bn + s1] = b;
        g_pos[b * 2 + 1] = i1 * Bn + s1;
        g_wk[b * 2 + 1] = w1;
    }
}

// ---------------- fp16 single-MMA compute (proven R15/R16): A plane @sbuf, B plane @sbuf+AP ----------------
// MT m-subtiles of 16 rows; 4 n-subtiles of 8 cols per warp (warp_n covers 32 cols).
template <int MT, int AP>
__device__ __forceinline__ void compute_tile_f16(uint32_t sbuf, int lane, int warp_m, int warp_n,
                                                 float acc[MT][4][4]) {
    uint32_t Af = sbuf, Bf = sbuf + AP;
    int rsel = lane & 7, grp = lane >> 3;
#pragma unroll
    for (int ks = 0; ks < 2; ks++) {
        uint32_t bf[4][2];
#pragma unroll
        for (int p = 0; p < 2; p++) {
            int nt = 2 * p + (grp >> 1);
            int n = warp_n * 32 + nt * 8 + rsel;
            int cB = 2 * ks + (grp & 1);
            uint32_t off = (uint32_t)n * 64 + (uint32_t)((cB ^ SWZ_R(n)) << 4);
            ldsm_x4(bf[2 * p][0], bf[2 * p][1], bf[2 * p + 1][0], bf[2 * p + 1][1], Bf + off);
        }
#pragma unroll
        for (int mt = 0; mt < MT; mt++) {
            int r = warp_m * (MT * 16) + mt * 16 + ((grp & 1) << 3) + rsel;
            int cA = 2 * ks + (grp >> 1);
            uint32_t off = (uint32_t)r * 64 + (uint32_t)((cA ^ SWZ_R(r)) << 4);
            uint32_t af[4];
            ldsm_x4(af[0], af[1], af[2], af[3], Af + off);
#pragma unroll
            for (int nt = 0; nt < 4; nt++)
                mma_f16(acc[mt][nt], af, bf[nt]);
        }
    }
}

// ======================= GEMM1 (byte-identical to R16, proven): fp16, M=128/N=64, split-load =======================
__global__ void __launch_bounds__(256, 2) gemm1_mma(const float* __restrict__ x,
                                                    const float* __restrict__ W1,
                                                    const float* __restrict__ b1) {
    extern __shared__ char smem[];
    uint32_t sbase = (uint32_t)__cvta_generic_to_shared(smem);
    int tid = threadIdx.x, wid = tid >> 5, lane = tid & 31;
    int warp_m = wid & 3, warp_n = wid >> 2;

    int e = blockIdx.z;
    int count = g_counts[e];
    int m0 = blockIdx.y * 128;
    if (m0 >= count) return;
    int n0 = blockIdx.x * 64;

    const float* W1e = W1 + (size_t)e * In * Hn;
    const int* tokp = g_tok + e * Bn;

    float acc[2][4][4];
#pragma unroll
    for (int i = 0; i < 2; i++)
#pragma unroll
        for (int j = 0; j < 4; j++)
#pragma unroll
            for (int k = 0; k < 4; k++) acc[i][j][k] = 0.f;

    int arow0 = tid >> 2, ach = tid & 3;
    int gr0 = m0 + arow0, gr1 = m0 + arow0 + 64;
    int tok0 = tokp[gr0 < count ? gr0 : count - 1];
    int tok1 = tokp[gr1 < count ? gr1 : count - 1];
    const float* Asrc0 = x + (size_t)tok0 * In + ach * 8;
    const float* Asrc1 = x + (size_t)tok1 * In + ach * 8;
    uint32_t adst0 = (uint32_t)arow0 * 64 + (uint32_t)((ach ^ SWZ_R(arow0)) * 16);
    uint32_t adst1 = (uint32_t)(arow0 + 64) * 64 + (uint32_t)((ach ^ SWZ_R(arow0 + 64)) * 16);
    int bn = tid & 63, bkg = tid >> 6;
    uint32_t bdst = (uint32_t)bn * 64 + (uint32_t)((bkg ^ SWZ_R(bn)) * 16);

    float fA[16], fB[8];

    auto ld = [&](int kt) {
        float4 v0 = *reinterpret_cast<const float4*>(Asrc0 + kt);
        float4 v1 = *reinterpret_cast<const float4*>(Asrc0 + kt + 4);
        fA[0] = v0.x; fA[1] = v0.y; fA[2] = v0.z; fA[3] = v0.w;
        fA[4] = v1.x; fA[5] = v1.y; fA[6] = v1.z; fA[7] = v1.w;
        float4 v2 = *reinterpret_cast<const float4*>(Asrc1 + kt);
        float4 v3 = *reinterpret_cast<const float4*>(Asrc1 + kt + 4);
        fA[8] = v2.x; fA[9] = v2.y; fA[10] = v2.z; fA[11] = v2.w;
        fA[12] = v3.x; fA[13] = v3.y; fA[14] = v3.z; fA[15] = v3.w;
        const float* src = W1e + (size_t)(kt + bkg * 8) * Hn + n0 + bn;
#pragma unroll
        for (int j = 0; j < 8; j++) fB[j] = src[(size_t)j * Hn];
    };
    auto st = [&](int b) {
        char* base = smem + b * BUF1_B;
        uint32_t hv[4];
#pragma unroll
        for (int half = 0; half < 2; half++) {
#pragma unroll
            for (int j = 0; j < 4; j++)
                hv[j] = pack2h(fA[half * 8 + 2 * j], fA[half * 8 + 2 * j + 1]);
            uint32_t ad = half ? adst1 : adst0;
            *reinterpret_cast<uint4*>(base + ad) = make_uint4(hv[0], hv[1], hv[2], hv[3]);
        }
#pragma unroll
        for (int j = 0; j < 4; j++)
            hv[j] = pack2h(fB[2 * j], fB[2 * j + 1]);
        *reinterpret_cast<uint4*>(base + PLANE_A1 + bdst) = make_uint4(hv[0], hv[1], hv[2], hv[3]);
    };

    const int NC = In / 32;    // 16
    ld(0); st(0);
    __syncthreads();
    for (int c = 0; c < NC; c++) {
        bool pre = (c + 1 < NC);
        if (pre) ld((c + 1) * 32);
        compute_tile_f16<2, PLANE_A1>(sbase + (uint32_t)((c & 1) * BUF1_B), lane, warp_m, warp_n, acc);
        if (pre) st((c + 1) & 1);
        __syncthreads();
    }

#pragma unroll
    for (int mt = 0; mt < 2; mt++) {
        int row_l = warp_m * 32 + mt * 16 + (lane >> 2);
#pragma unroll
        for (int nt = 0; nt < 4; nt++) {
            int ncol_l = warp_n * 32 + nt * 8 + (lane & 3) * 2;
            float bb0 = b1[e * Hn + n0 + ncol_l];
            float bb1 = b1[e * Hn + n0 + ncol_l + 1];
#pragma unroll
            for (int h = 0; h < 2; h++) {
                int grow = m0 + row_l + h * 8;
                float v0 = fmaxf(acc[mt][nt][h * 2 + 0] + bb0, 0.f);
                float v1 = fmaxf(acc[mt][nt][h * 2 + 1] + bb1, 0.f);
                size_t off = (size_t)(e * Bn + grow) * Hn + n0 + ncol_l;
                *reinterpret_cast<uint32_t*>(g_hf16 + off) = pack2h(v0, v1);
            }
        }
    }
}

// ======================= GEMM2: fp16, M=64 x N=128, warps 2m x 4n (MT=2), K-split-4, 3-stage cp.async =======================
__global__ void __launch_bounds__(256, 3) gemm2_mma(const float* __restrict__ W2) {
    extern __shared__ char smem[];
    uint32_t sbase = (uint32_t)__cvta_generic_to_shared(smem);
    int tid = threadIdx.x, wid = tid >> 5, lane = tid & 31;
    int warp_m = wid & 1, warp_n = wid >> 1;     // 2 m-warps x 4 n-warps

    int e = blockIdx.z;
    int count = g_counts[e];
    int kh = blockIdx.y & 3;
    int m0 = (blockIdx.y >> 2) * 64;
    if (m0 >= count) return;
    int n0 = blockIdx.x * 128;
    int kbase = kh * (Hn / 4);                   // 0, 512, 1024, 1536

    const __half* Ag = g_hf16 + (size_t)(e * Bn + m0) * Hn + kbase;
    const float* W2e = W2 + (size_t)e * Hn * On + (size_t)kbase * On;
    float* yout = g_yall + (size_t)kh * EBO;

    float acc[2][4][4];
#pragma unroll
    for (int i = 0; i < 2; i++)
#pragma unroll
        for (int j = 0; j < 4; j++)
#pragma unroll
            for (int k = 0; k < 4; k++) acc[i][j][k] = 0.f;

    // A: 64 rows x 4 chunks = 256 -> 1 CP16 per thread per plane-chunk
    int arow = tid >> 2, ach = tid & 3;
    uint32_t adst = (uint32_t)arow * 64 + (uint32_t)((ach ^ SWZ_R(arow)) * 16);
    // B: 128 n x 4 chunks = 512 slots; thread handles n = tid&127, chunks {tid>>7, (tid>>7)+2}
    int bn = tid & 127, bc0 = tid >> 7;          // bc0 in {0,1}; second chunk bc0+2
    uint32_t bdst0 = (uint32_t)bn * 64 + (uint32_t)(((bc0)     ^ SWZ_R(bn)) * 16);
    uint32_t bdst1 = (uint32_t)bn * 64 + (uint32_t)(((bc0 + 2) ^ SWZ_R(bn)) * 16);

    float fB[16];

    auto aload = [&](int b, int kt) {
        size_t src = (size_t)arow * Hn + kt + ach * 8;
        CP16(sbase + (uint32_t)(b * BUF2_B) + adst, Ag + src);
    };
    auto bload = [&](int kt) {
        const float* s0 = W2e + (size_t)(kt + bc0 * 8) * On + n0 + bn;
        const float* s1 = W2e + (size_t)(kt + (bc0 + 2) * 8) * On + n0 + bn;
#pragma unroll
        for (int j = 0; j < 8; j++) fB[j]     = s0[(size_t)j * On];
#pragma unroll
        for (int j = 0; j < 8; j++) fB[8 + j] = s1[(size_t)j * On];
    };
    auto bstore = [&](int b) {
        char* base = smem + b * BUF2_B + PLANE_A2;
        uint32_t hv[4];
#pragma unroll
        for (int j = 0; j < 4; j++) hv[j] = pack2h(fB[2 * j], fB[2 * j + 1]);
        *reinterpret_cast<uint4*>(base + bdst0) = make_uint4(hv[0], hv[1], hv[2], hv[3]);
#pragma unroll
        for (int j = 0; j < 4; j++) hv[j] = pack2h(fB[8 + 2 * j], fB[8 + 2 * j + 1]);
        *reinterpret_cast<uint4*>(base + bdst1) = make_uint4(hv[0], hv[1], hv[2], hv[3]);
    };

    const int NC = (Hn / 4) / 32;    // 16

    bload(0);  aload(0, 0);  CPCOMMIT(); bstore(0);
    bload(32); aload(1, 32); CPCOMMIT(); bstore(1);

    for (int c = 0; c < NC; c++) {
        if (c + 1 < NC) { CPWAIT1(); } else { CPWAIT0(); }
        __syncthreads();
        bool pre = (c + 2 < NC);
        if (pre) {
            int kt2 = (c + 2) * 32;
            bload(kt2);
            aload((c + 2) % 3, kt2);
            CPCOMMIT();
        }
        compute_tile_f16<2, PLANE_A2>(sbase + (uint32_t)((c % 3) * BUF2_B), lane, warp_m, warp_n, acc);
        if (pre) bstore((c + 2) % 3);
    }

#pragma unroll
    for (int mt = 0; mt < 2; mt++) {
        int row_l = warp_m * 32 + mt * 16 + (lane >> 2);
#pragma unroll
        for (int nt = 0; nt < 4; nt++) {
            int ncol_l = warp_n * 32 + nt * 8 + (lane & 3) * 2;
#pragma unroll
            for (int h = 0; h < 2; h++) {
                int grow = m0 + row_l + h * 8;
                float2 v = make_float2(acc[mt][nt][h * 2 + 0], acc[mt][nt][h * 2 + 1]);
                *reinterpret_cast<float2*>(yout + (size_t)(e * Bn + grow) * On + n0 + ncol_l) = v;
            }
        }
    }
}

// ---------------- combine (+ b2), sums the four K-quarters ----------------
__global__ void combine_kernel(const float* __restrict__ b2, float* __restrict__ out) {
    int idx = blockIdx.x * 256 + threadIdx.x;
    int b = idx >> 7;
    int o = (idx & 127) * 4;
    int p0 = g_pos[b * 2 + 0], p1 = g_pos[b * 2 + 1];
    float w0 = g_wk[b * 2 + 0], w1 = g_wk[b * 2 + 1];
    int e0 = p0 >> 10, e1 = p1 >> 10;
    float4 s0 = *reinterpret_cast<const float4*>(b2 + (size_t)e0 * On + o);
    float4 s1 = *reinterpret_cast<const float4*>(b2 + (size_t)e1 * On + o);
#pragma unroll
    for (int q = 0; q < 4; q++) {
        const float* yq = g_yall + (size_t)q * EBO;
        float4 a = *reinterpret_cast<const float4*>(yq + (size_t)p0 * On + o);
        float4 c = *reinterpret_cast<const float4*>(yq + (size_t)p1 * On + o);
        s0.x += a.x; s0.y += a.y; s0.z += a.z; s0.w += a.w;
        s1.x += c.x; s1.y += c.y; s1.z += c.z; s1.w += c.w;
    }
    float4 r;
    r.x = w0 * s0.x + w1 * s1.x;
    r.y = w0 * s0.y + w1 * s1.y;
    r.z = w0 * s0.z + w1 * s1.z;
    r.w = w0 * s0.w + w1 * s1.w;
    *reinterpret_cast<float4*>(out + (size_t)b * On + o) = r;
}

// ---------------- launch ----------------
extern "C" void kernel_launch(void* const* d_in, const int* in_sizes, int n_in,
                              void* d_out, int out_size) {
    const float* x  = (const float*)d_in[0];
    const float* Wg = (const float*)d_in[1];
    const float* bg = (const float*)d_in[2];
    const float* W1 = (const float*)d_in[3];
    const float* b1 = (const float*)d_in[4];
    const float* W2 = (const float*)d_in[5];
    const float* b2 = (const float*)d_in[6];
    float* out = (float*)d_out;

    zero_counts_kernel<<<1, 32>>>();
    gate_kernel<<<Bn / 8, 256>>>(x, Wg, bg);
    gemm1_mma<<<dim3(Hn / 64, Bn / 128, En), 256, GSMEM1>>>(x, W1, b1);
    gemm2_mma<<<dim3(On / 128, (Bn / 64) * 4, En), 256, GSMEM2>>>(W2);
    combine_kernel<<<(Bn * On / 4) / 256, 256>>>(b2, out);
}